// round 7
// baseline (speedup 1.0000x reference)
#include <cuda_runtime.h>
#include <cuda_fp16.h>
#include <cstdint>

// ===== problem constants =====
#define RTOT  32768
#define CDIM  256
#define KTOT  8192
#define MT    128
#define NT    128
#define KSTEPS 16              // single product: hi*hi
#define NUM_MT (RTOT/MT)       // 256
#define NUM_NT (KTOT/NT)       // 64
#define JOBS  (NUM_MT*NUM_NT)  // 16384
#define NCTA  148
#define THREADS 512            // 16 warps, 4 per SMSP

#define SMEM_A    0
#define SMEM_B0   65536
#define SMEM_B1   131072
#define SMEM_TOTAL 196608      // A 64KB + B double buffer 2x64KB

#define IDX_OFF  8388608
#define DIST_OFF (8388608+32768)

#define VOFF 1024.0f
#define MARGIN 0.16f
#define FIXROWS 16

// ===== device globals (static scratch) =====
__device__ uint4 g_Aimg[(size_t)NUM_MT*4096];   // 16MB: [mtile][panel(16)][256 units] swizzled hi-fp16
__device__ uint4 g_Bimg[(size_t)NUM_NT*4096];   // 4MB
__device__ float g_cbsq[KTOT];
__device__ float g_cbsqo[KTOT];                 // cbsq + VOFF
__device__ float g_xsq[RTOT];
__device__ int   g_idx[RTOT];
__device__ unsigned long long g_best[RTOT];
__device__ unsigned int g_best2[RTOT];
__device__ int g_fixcnt;
__device__ int g_fixrows[RTOT];

// ===== helpers =====
__device__ __forceinline__ uint32_t smem_u32(const void* p) {
    uint32_t a;
    asm("{ .reg .u64 t; cvta.to.shared.u64 t, %1; cvt.u32.u64 %0, t; }" : "=r"(a) : "l"(p));
    return a;
}
__device__ __forceinline__ void cp_async16(uint32_t sa, const void* g) {
    asm volatile("cp.async.cg.shared.global [%0], [%1], 16;" :: "r"(sa), "l"(g));
}
#define CP_COMMIT() asm volatile("cp.async.commit_group;" ::: "memory")
#define CP_WAIT(N)  asm volatile("cp.async.wait_group %0;" :: "n"(N) : "memory")

__device__ __forceinline__ void ldsm4(uint32_t* r, uint32_t addr) {
    asm volatile("ldmatrix.sync.aligned.m8n8.x4.shared.b16 {%0,%1,%2,%3}, [%4];"
        : "=r"(r[0]), "=r"(r[1]), "=r"(r[2]), "=r"(r[3]) : "r"(addr));
}
__device__ __forceinline__ void mma16816(float* c, const uint32_t* a, uint32_t b0, uint32_t b1) {
    asm volatile("mma.sync.aligned.m16n8k16.row.col.f32.f16.f16.f32 "
        "{%0,%1,%2,%3}, {%4,%5,%6,%7}, {%8,%9}, {%0,%1,%2,%3};"
        : "+f"(c[0]), "+f"(c[1]), "+f"(c[2]), "+f"(c[3])
        : "r"(a[0]), "r"(a[1]), "r"(a[2]), "r"(a[3]), "r"(b0), "r"(b1));
}
__device__ __forceinline__ uint32_t encf(float f) {
    uint32_t u = __float_as_uint(f);
    return (u & 0x80000000u) ? ~u : (u | 0x80000000u);
}
__device__ __forceinline__ float decf(uint32_t e) {
    uint32_t u = (e & 0x80000000u) ? (e & 0x7fffffffu) : ~e;
    return __uint_as_float(u);
}
__device__ __forceinline__ uint32_t packh2(__half a, __half b) {
    __half2 h = __halves2half2(a, b);
    return *reinterpret_cast<uint32_t*>(&h);
}

// ===== small kernels =====
__global__ void init_kernel() {
    int i = blockIdx.x * 256 + threadIdx.x;
    g_best[i] = ~0ull;
    g_best2[i] = 0xFFFFFFFFu;
    if (i == 0) g_fixcnt = 0;
}

__global__ void rowsq_kernel(const float* __restrict__ in, int rows, int which) {
    int gw = (blockIdx.x * blockDim.x + threadIdx.x) >> 5;
    int lane = threadIdx.x & 31;
    if (gw >= rows) return;
    const float4* p = reinterpret_cast<const float4*>(in) + (size_t)gw * (CDIM / 4);
    float s = 0.f;
#pragma unroll
    for (int k = 0; k < 2; ++k) {
        float4 v = p[lane + 32 * k];
        s += v.x*v.x + v.y*v.y + v.z*v.z + v.w*v.w;
    }
#pragma unroll
    for (int o = 16; o; o >>= 1) s += __shfl_xor_sync(0xffffffffu, s, o);
    if (lane == 0) {
        if (which == 0) g_xsq[gw] = s;
        else { g_cbsq[gw] = s; g_cbsqo[gw] = s + VOFF; }
    }
}

// hi-fp16 pre-swizzled image: 16 panels of [tile-row 128 x k16]
__device__ __forceinline__ void prep_unit(const float* __restrict__ src, int t, uint4* img) {
    int row = t >> 5, u = t & 31;
    int ks = u >> 1, kh = u & 1;
    int kext = ks * 16 + kh * 8;
    const float* r = src + (size_t)row * CDIM;
    __half h[8];
#pragma unroll
    for (int i = 0; i < 8; ++i) h[i] = __float2half(r[kext + i]);
    uint4 val;
    val.x = packh2(h[0], h[1]); val.y = packh2(h[2], h[3]);
    val.z = packh2(h[4], h[5]); val.w = packh2(h[6], h[7]);
    int tile = row >> 7, rl = row & 127;
    int phys = (rl * 2 + kh) ^ ((rl >> 2) & 1);
    img[(size_t)tile * 4096 + ks * 256 + phys] = val;
}

__global__ void prep_a_kernel(const float* __restrict__ x) {
    prep_unit(x, blockIdx.x * 256 + threadIdx.x, g_Aimg);
}
__global__ void prep_b_kernel(const float* __restrict__ cb) {
    prep_unit(cb, blockIdx.x * 256 + threadIdx.x, g_Bimg);
}

// ===== main HMMA kernel (512 threads) =====
__device__ __forceinline__ void issue_Bjob(uint32_t smemB, int nt, int tid) {
    const uint4* src = g_Bimg + (size_t)nt * 4096 + tid;
#pragma unroll
    for (int i = 0; i < 8; ++i)
        cp_async16(smemB + (tid + i * 512) * 16, src + i * 512);
}
__device__ __forceinline__ void issue_A(uint32_t smemA, int m, int tid) {
    const uint4* src = g_Aimg + (size_t)m * 4096 + tid;
#pragma unroll
    for (int i = 0; i < 8; ++i)
        cp_async16(smemA + (tid + i * 512) * 16, src + i * 512);
}

__global__ __launch_bounds__(THREADS, 1)
void vq_hmma_kernel() {
    extern __shared__ char smem[];
    uint32_t sb = smem_u32(smem);
    uint32_t smA = sb + SMEM_A;
    uint32_t smB[2] = { sb + SMEM_B0, sb + SMEM_B1 };

    int tid = threadIdx.x;
    int l = tid & 31, w = tid >> 5;
    int wm = w >> 1, wn = w & 1;      // wm: 8 row-slices of 16; wn: 2 col-halves of 64

    // per-thread ldmatrix offsets (bytes inside a 4KB panel)
    uint32_t aoff, boff[4];
    {
        int row = wm * 16 + (l & 15);
        int kh = l >> 4;
        aoff = (uint32_t)(((row * 2 + kh) ^ ((row >> 2) & 1)) << 4);
    }
#pragma unroll
    for (int nt4 = 0; nt4 < 4; ++nt4) {
        int code = wn * 64 + nt4 * 16 + (l & 7) + ((l >> 4) << 3);
        int kh = (l >> 3) & 1;
        boff[nt4] = (uint32_t)(((code * 2 + kh) ^ ((code >> 2) & 1)) << 4);
    }

    int start = (int)(((long long)blockIdx.x * JOBS) / NCTA);
    int end   = (int)(((long long)(blockIdx.x + 1) * JOBS) / NCTA);

    int cur_m = start >> 6;
    issue_A(smA, cur_m, tid); CP_COMMIT();
    issue_Bjob(smB[0], start & 63, tid); CP_COMMIT();
    CP_WAIT(0);
    __syncthreads();
    int buf = 0;

    // running per-row argmin state, indexed [h]; values offset by VOFF
    float rb[2] = {3.4e38f, 3.4e38f};
    float rs[2] = {3.4e38f, 3.4e38f};
    int   ri[2] = {0, 0};

    for (int j = start; j < end; ++j) {
        int ntj = j & 63;
        int jn = j + 1;
        bool nx_same = (jn < end) && ((jn >> 6) == cur_m);

        // prefetch next job's B into the other buffer (overlaps full job)
        if (nx_same) { issue_Bjob(smB[buf ^ 1], jn & 63, tid); CP_COMMIT(); }

        // prefetch offset |c|^2 for this thread's 16 columns
        float qv[16];
        int qbase = ntj * 128 + wn * 64 + (l & 3) * 2;
#pragma unroll
        for (int nb = 0; nb < 8; ++nb) {
            qv[nb * 2]     = __ldg(&g_cbsqo[qbase + nb * 8]);
            qv[nb * 2 + 1] = __ldg(&g_cbsqo[qbase + nb * 8 + 1]);
        }

        float acc[8][4];
#pragma unroll
        for (int nb = 0; nb < 8; ++nb)
#pragma unroll
            for (int q = 0; q < 4; ++q) acc[nb][q] = 0.f;

        uint32_t Bbase = smB[buf];
#pragma unroll
        for (int ks = 0; ks < KSTEPS; ++ks) {
            uint32_t Apan = smA + ks * 4096;
            uint32_t Bpan = Bbase + ks * 4096;
            uint32_t af[4], bf[4][4];
            ldsm4(af, Apan + aoff);
#pragma unroll
            for (int nt4 = 0; nt4 < 4; ++nt4) ldsm4(bf[nt4], Bpan + boff[nt4]);
#pragma unroll
            for (int nt4 = 0; nt4 < 4; ++nt4) {
                mma16816(acc[nt4*2  ], af, bf[nt4][0], bf[nt4][1]);
                mma16816(acc[nt4*2+1], af, bf[nt4][2], bf[nt4][3]);
            }
        }

        // ---- epilogue: packed-key min + exact second, branchless ----
#pragma unroll
        for (int h = 0; h < 2; ++h) {
            uint32_t k1 = 0xFFFFFFFFu, k2 = 0xFFFFFFFFu;
#pragma unroll
            for (int nb = 0; nb < 8; ++nb)
#pragma unroll
                for (int c = 0; c < 2; ++c) {
                    float v = fmaf(-2.f, acc[nb][h * 2 + c], qv[nb * 2 + c]);
                    uint32_t k = (__float_as_uint(v) & 0xFFFFFFF0u) | (uint32_t)(nb * 2 + c);
                    uint32_t t = max(k1, k);
                    k1 = min(k1, k);
                    k2 = min(k2, t);
                }
            float v1 = __uint_as_float(k1 & 0xFFFFFFF0u);
            float v2 = __uint_as_float(k2 & 0xFFFFFFF0u);
            int li = (int)(k1 & 15u);
            int gidx = qbase + (li >> 1) * 8 + (li & 1);
            if (v1 < rb[h]) {
                rs[h] = fminf(rb[h], v2);
                rb[h] = v1; ri[h] = gidx;
            } else {
                rs[h] = fminf(rs[h], v1);
            }
        }

        bool m_change = (jn < end) && !nx_same;
        if (m_change || jn == end) {
            // flush 2 rows: quad-merge then atomic dance
#pragma unroll
            for (int h = 0; h < 2; ++h) {
                float bv = rb[h], sv = rs[h];
                int bi = ri[h];
#pragma unroll
                for (int o = 1; o < 4; o <<= 1) {
                    float ov = __shfl_xor_sync(0xffffffffu, bv, o);
                    int   oi = __shfl_xor_sync(0xffffffffu, bi, o);
                    float os = __shfl_xor_sync(0xffffffffu, sv, o);
                    if (ov < bv || (ov == bv && oi < bi)) {
                        sv = fminf(bv, os); bv = ov; bi = oi;
                    } else {
                        sv = fminf(sv, ov);
                    }
                }
                if ((l & 3) == 0) {
                    int r = cur_m * MT + wm * 16 + h * 8 + (l >> 2);
                    unsigned long long key =
                        ((unsigned long long)encf(bv) << 32) | (uint32_t)bi;
                    unsigned long long old = atomicMin(&g_best[r], key);
                    uint32_t oldenc = (uint32_t)(old >> 32);
                    uint32_t be = encf(bv);
                    uint32_t cand = min(encf(sv), max(be, oldenc));
                    atomicMin(&g_best2[r], cand);
                }
                rb[h] = 3.4e38f; rs[h] = 3.4e38f; ri[h] = 0;
            }
        }

        if (nx_same) {
            CP_WAIT(0);
            __syncthreads();
            buf ^= 1;
        } else if (jn < end) {
            __syncthreads();          // all warps done reading A
            cur_m = jn >> 6;
            issue_A(smA, cur_m, tid); CP_COMMIT();
            issue_Bjob(smB[buf], jn & 63, tid); CP_COMMIT();
            CP_WAIT(0);
            __syncthreads();
        }
    }
}

// ===== finalize: decode, flag rows with small approx gap =====
__global__ void final_kernel(float* __restrict__ out) {
    int i = blockIdx.x * 256 + threadIdx.x;
    unsigned long long key = g_best[i];
    int idx = (int)(uint32_t)key;
    float val = decf((uint32_t)(key >> 32)) - VOFF;
    float sec = decf(g_best2[i]) - VOFF;
    out[IDX_OFF + i]  = (float)idx;
    out[DIST_OFF + i] = g_xsq[i] + val;
    g_idx[i] = idx;
    if (sec - val < MARGIN) {
        int p = atomicAdd(&g_fixcnt, 1);
        g_fixrows[p] = i;
    }
}

// ===== exact fp32 rescan for flagged rows: 16 rows/block, 4x4 reg tiles =====
__global__ __launch_bounds__(256) void fixup_kernel(const float* __restrict__ x,
                                                    const float* __restrict__ cb,
                                                    float* __restrict__ out) {
    __shared__ float4 xs[FIXROWS][64];
    __shared__ unsigned long long wk[FIXROWS][2];
    int tid = threadIdx.x;
    int n = g_fixcnt;
    int ngroups = (n + FIXROWS - 1) / FIXROWS;
    const float4* c4 = reinterpret_cast<const float4*>(cb);
    for (int g = blockIdx.x; g < ngroups; g += gridDim.x) {
        __syncthreads();
        for (int i = tid; i < FIXROWS * 64; i += 256) {
            int r = i >> 6, q = i & 63;
            int fr = g * FIXROWS + r;
            int row = g_fixrows[(fr < n) ? fr : g * FIXROWS];
            xs[r][q] = reinterpret_cast<const float4*>(x)[(size_t)row * 64 + q];
        }
        __syncthreads();
        int rg = tid >> 6;            // 4 row-groups of 4 rows
        int cg = tid & 63;
        float bv[4] = {3.4e38f,3.4e38f,3.4e38f,3.4e38f};
        int   bi[4] = {0,0,0,0};
        for (int k = 0; k < 32; ++k) {
            int c0 = k * 256 + cg * 4;
            float acc[4][4];
#pragma unroll
            for (int r = 0; r < 4; ++r)
#pragma unroll
                for (int cc = 0; cc < 4; ++cc) acc[r][cc] = 0.f;
#pragma unroll 8
            for (int q = 0; q < 64; ++q) {
                float4 xv[4];
#pragma unroll
                for (int r = 0; r < 4; ++r) xv[r] = xs[rg * 4 + r][q];
#pragma unroll
                for (int cc = 0; cc < 4; ++cc) {
                    float4 v = c4[(size_t)(c0 + cc) * 64 + q];
#pragma unroll
                    for (int r = 0; r < 4; ++r) {
                        acc[r][cc] = fmaf(v.x, xv[r].x, acc[r][cc]);
                        acc[r][cc] = fmaf(v.y, xv[r].y, acc[r][cc]);
                        acc[r][cc] = fmaf(v.z, xv[r].z, acc[r][cc]);
                        acc[r][cc] = fmaf(v.w, xv[r].w, acc[r][cc]);
                    }
                }
            }
#pragma unroll
            for (int cc = 0; cc < 4; ++cc) {
                float cq = __ldg(&g_cbsq[c0 + cc]);
#pragma unroll
                for (int r = 0; r < 4; ++r) {
                    float val = fmaf(-2.f, acc[r][cc], cq);
                    if (val < bv[r] || (val == bv[r] && c0 + cc < bi[r])) {
                        bv[r] = val; bi[r] = c0 + cc;
                    }
                }
            }
        }
        // reduce: warp shfl-min on packed keys, 2 warps per row-group
#pragma unroll
        for (int r = 0; r < 4; ++r) {
            unsigned long long key =
                ((unsigned long long)encf(bv[r]) << 32) | (uint32_t)bi[r];
#pragma unroll
            for (int o = 16; o; o >>= 1) {
                unsigned long long ok = __shfl_xor_sync(0xffffffffu, key, o);
                key = min(key, ok);
            }
            if ((tid & 31) == 0) wk[rg * 4 + r][(tid >> 5) & 1] = key;
        }
        __syncthreads();
        if (tid < FIXROWS) {
            int fr = g * FIXROWS + tid;
            if (fr < n) {
                unsigned long long best = min(wk[tid][0], wk[tid][1]);
                int row = g_fixrows[fr];
                int idx = (int)(uint32_t)best;
                out[IDX_OFF + row]  = (float)idx;
                out[DIST_OFF + row] = g_xsq[row] + decf((uint32_t)(best >> 32));
                g_idx[row] = idx;
            }
        }
    }
}

// ===== gather codes =====
__global__ void gather_kernel(const float* __restrict__ cb, float* __restrict__ out) {
    int tid = threadIdx.x;
    int row = blockIdx.x * 4 + (tid >> 6);
    int c = tid & 63;
    int idx = g_idx[row];
    reinterpret_cast<float4*>(out)[(size_t)row * 64 + c] =
        reinterpret_cast<const float4*>(cb)[(size_t)idx * 64 + c];
}

extern "C" void kernel_launch(void* const* d_in, const int* in_sizes, int n_in,
                              void* d_out, int out_size) {
    const float* x  = (const float*)d_in[0];   // z_e_x  [8,4096,256] f32
    const float* cb = (const float*)d_in[1];   // codebook [8192,256] f32
    float* out = (float*)d_out;                // codes | idx | distances (f32)

    cudaFuncSetAttribute(vq_hmma_kernel,
                         cudaFuncAttributeMaxDynamicSharedMemorySize, SMEM_TOTAL);

    init_kernel<<<RTOT / 256, 256>>>();
    rowsq_kernel<<<(RTOT * 32) / 256, 256>>>(x, RTOT, 0);
    rowsq_kernel<<<(KTOT * 32) / 256, 256>>>(cb, KTOT, 1);
    prep_a_kernel<<<(RTOT * 32) / 256, 256>>>(x);
    prep_b_kernel<<<(KTOT * 32) / 256, 256>>>(cb);
    vq_hmma_kernel<<<NCTA, THREADS, SMEM_TOTAL>>>();
    final_kernel<<<RTOT / 256, 256>>>(out);
    fixup_kernel<<<NCTA, 256>>>(x, cb, out);
    gather_kernel<<<RTOT / 4, 256>>>(cb, out);
}